// round 1
// baseline (speedup 1.0000x reference)
#include <cuda_runtime.h>
#include <math.h>

// Problem constants (reference hardcodes H=W=512, N=4096).
#define NG     4096
#define HIMG   512
#define WIMG   512
#define HW     (HIMG * WIMG)
#define TILE   16
#define TXN    (WIMG / TILE)   // 32 tiles in x
#define TYN    (HIMG / TILE)   // 32 tiles in y
#define NTILES (TXN * TYN)     // 1024
#define CAP    4096            // worst case: every gaussian in one tile
#define BATCH  256

// Static device scratch (no allocations allowed in kernel_launch).
__device__ float4 g_pa[NG];                 // px, py, 0.5*c0, c1
__device__ float4 g_pb[NG];                 // 0.5*c2, feat_r, feat_g, feat_b
__device__ float4 g_pc[NG];                 // geo_r, geo_g, geo_b, unused
__device__ int    g_tile_cnt[NTILES];
__device__ int    g_tile_list[NTILES * CAP];

__global__ void zero_counters_kernel() {
    int i = blockIdx.x * blockDim.x + threadIdx.x;
    if (i < NTILES) g_tile_cnt[i] = 0;
}

__global__ __launch_bounds__(256)
void project_bin_kernel(const float* __restrict__ xyz,
                        const float* __restrict__ chol,
                        const float* __restrict__ feat,
                        const float* __restrict__ rcol,
                        float* __restrict__ opac_out) {
    int i = blockIdx.x * blockDim.x + threadIdx.x;
    if (i >= NG) return;

    opac_out[i] = 1.0f;  // opac output = ones(N,1)

    float mx = tanhf(xyz[2 * i + 0]);
    float my = tanhf(xyz[2 * i + 1]);

    float l0 = chol[3 * i + 0] + 0.5f;
    float l1 = chol[3 * i + 1];
    float l2 = chol[3 * i + 2] + 0.5f;

    float s00 = l0 * l0;
    float s01 = l0 * l1;
    float s11 = l1 * l1 + l2 * l2;
    float det = s00 * s11 - s01 * s01;
    float inv = 1.0f / det;
    float c0 =  s11 * inv;
    float c1 = -s01 * inv;
    float c2 =  s00 * inv;

    float px = 0.5f * ((mx + 1.0f) * (float)WIMG - 1.0f);
    float py = 0.5f * ((my + 1.0f) * (float)HIMG - 1.0f);

    g_pa[i] = make_float4(px, py, 0.5f * c0, c1);
    g_pb[i] = make_float4(0.5f * c2, feat[3 * i], feat[3 * i + 1], feat[3 * i + 2]);
    g_pc[i] = make_float4(0.5f * rcol[3 * i], 0.5f * rcol[3 * i + 1],
                          0.5f * rcol[3 * i + 2], 0.0f);

    // Conservative bbox: contribution requires sigma <= ln(255) ~ 5.5413.
    // x-extent of {0.5 d^T C d <= T} is sqrt(2 T s00); add margin.
    const float T = 5.65f;
    float hx = sqrtf(2.0f * T * s00) + 1.0f;
    float hy = sqrtf(2.0f * T * s11) + 1.0f;

    if (px + hx < 0.0f || px - hx > (float)(WIMG - 1) ||
        py + hy < 0.0f || py - hy > (float)(HIMG - 1)) return;

    int x0 = max(0,       (int)floorf((px - hx) * (1.0f / TILE)));
    int x1 = min(TXN - 1, (int)floorf((px + hx) * (1.0f / TILE)));
    int y0 = max(0,       (int)floorf((py - hy) * (1.0f / TILE)));
    int y1 = min(TYN - 1, (int)floorf((py + hy) * (1.0f / TILE)));

    for (int ty = y0; ty <= y1; ty++) {
        for (int tx = x0; tx <= x1; tx++) {
            int t = ty * TXN + tx;
            int slot = atomicAdd(&g_tile_cnt[t], 1);
            // slot < CAP always (cnt <= NG == CAP), no guard needed, but be safe:
            if (slot < CAP) g_tile_list[t * CAP + slot] = i;
        }
    }
}

__global__ __launch_bounds__(256)
void raster_kernel(float* __restrict__ out) {
    __shared__ float4 sa[BATCH];
    __shared__ float4 sb[BATCH];
    __shared__ float4 sc[BATCH];

    int tile  = blockIdx.x;
    int tilex = tile % TXN;
    int tiley = tile / TXN;
    int tid   = threadIdx.x;
    int lx    = tid & (TILE - 1);
    int ly    = tid >> 4;

    int   pxi = tilex * TILE + lx;
    int   pyi = tiley * TILE + ly;
    float pxf = (float)pxi;
    float pyf = (float)pyi;

    int cnt = g_tile_cnt[tile];
    if (cnt > CAP) cnt = CAP;

    float ar = 0.f, ag = 0.f, ab = 0.f;
    float gr = 0.f, gg = 0.f, gb = 0.f;
    float aa = 0.f;

    for (int base = 0; base < cnt; base += BATCH) {
        int n = min(BATCH, cnt - base);
        __syncthreads();
        for (int j = tid; j < n; j += 256) {
            int id = g_tile_list[tile * CAP + base + j];
            sa[j] = g_pa[id];
            sb[j] = g_pb[id];
            sc[j] = g_pc[id];
        }
        __syncthreads();
        for (int j = 0; j < n; j++) {
            float4 a = sa[j];
            float dx = a.x - pxf;
            float dy = a.y - pyf;
            float c2h = sb[j].x;
            float sigma = a.z * dx * dx + a.w * dx * dy + c2h * dy * dy;
            float e = expf(-sigma);
            float alpha = fminf(0.999f, e);
            bool live = (sigma >= 0.0f) && (alpha >= (1.0f / 255.0f));
            if (live) {
                float4 b = sb[j];
                float4 c = sc[j];
                ar += alpha * b.y;
                ag += alpha * b.z;
                ab += alpha * b.w;
                gr += alpha * c.x;
                gg += alpha * c.y;
                gb += alpha * c.z;
                aa += alpha;
            }
        }
    }

    int pix = pyi * WIMG + pxi;
    // render (clipped), channel-major [3, H, W]
    out[0 * HW + pix] = fminf(1.0f, fmaxf(0.0f, ar));
    out[1 * HW + pix] = fminf(1.0f, fmaxf(0.0f, ag));
    out[2 * HW + pix] = fminf(1.0f, fmaxf(0.0f, ab));
    // gauss_render (clipped)
    out[3 * HW + pix] = fminf(1.0f, fmaxf(0.0f, gr));
    out[4 * HW + pix] = fminf(1.0f, fmaxf(0.0f, gg));
    out[5 * HW + pix] = fminf(1.0f, fmaxf(0.0f, gb));
    // alpha map (unclipped)
    out[6 * HW + pix] = aa;
}

extern "C" void kernel_launch(void* const* d_in, const int* in_sizes, int n_in,
                              void* d_out, int out_size) {
    const float* xyz  = (const float*)d_in[0];
    const float* chol = (const float*)d_in[1];
    const float* feat = (const float*)d_in[2];
    const float* rcol = (const float*)d_in[3];
    // d_in[4], d_in[5] are H, W scalars (compile-time 512 here).

    float* out  = (float*)d_out;
    float* opac = out + 7 * HW;  // render(3HW) + gauss(3HW) + alpha(HW), then opac(NG)

    zero_counters_kernel<<<1, NTILES>>>();
    project_bin_kernel<<<(NG + 255) / 256, 256>>>(xyz, chol, feat, rcol, opac);
    raster_kernel<<<NTILES, 256>>>(out);
}

// round 2
// speedup vs baseline: 1.1165x; 1.1165x over previous
#include <cuda_runtime.h>
#include <math.h>

// Problem constants (reference hardcodes H=W=512, N=4096).
#define NG     4096
#define HIMG   512
#define WIMG   512
#define HW     (HIMG * WIMG)
#define TILE   16
#define TXN    (WIMG / TILE)   // 32 tiles in x
#define TYN    (HIMG / TILE)   // 32 tiles in y
#define NTILES (TXN * TYN)     // 1024
#define CAP    4096            // worst case: every gaussian in one tile
#define BATCH  256

// Static device scratch (zero-initialized at load; raster restores zeros so
// every graph replay sees the same initial state).
__device__ float4 g_pa[NG];                 // px, py, 0.5*c0, c1
__device__ float4 g_pb[NG];                 // 0.5*c2, feat_r, feat_g, feat_b
__device__ float4 g_pc[NG];                 // geo_r, geo_g, geo_b, unused
__device__ int    g_tile_cnt[NTILES];
__device__ int    g_tile_list[NTILES * CAP];

__global__ __launch_bounds__(256)
void project_bin_kernel(const float* __restrict__ xyz,
                        const float* __restrict__ chol,
                        const float* __restrict__ feat,
                        const float* __restrict__ rcol,
                        float* __restrict__ opac_out) {
    int i = blockIdx.x * blockDim.x + threadIdx.x;
    if (i >= NG) return;

    opac_out[i] = 1.0f;  // opac output = ones(N,1)

    float mx = tanhf(xyz[2 * i + 0]);
    float my = tanhf(xyz[2 * i + 1]);

    float l0 = chol[3 * i + 0] + 0.5f;
    float l1 = chol[3 * i + 1];
    float l2 = chol[3 * i + 2] + 0.5f;

    float s00 = l0 * l0;
    float s01 = l0 * l1;
    float s11 = l1 * l1 + l2 * l2;
    float det = s00 * s11 - s01 * s01;
    float inv = 1.0f / det;
    float c0 =  s11 * inv;
    float c1 = -s01 * inv;
    float c2 =  s00 * inv;

    float px = 0.5f * ((mx + 1.0f) * (float)WIMG - 1.0f);
    float py = 0.5f * ((my + 1.0f) * (float)HIMG - 1.0f);

    g_pa[i] = make_float4(px, py, 0.5f * c0, c1);
    g_pb[i] = make_float4(0.5f * c2, feat[3 * i], feat[3 * i + 1], feat[3 * i + 2]);
    g_pc[i] = make_float4(0.5f * rcol[3 * i], 0.5f * rcol[3 * i + 1],
                          0.5f * rcol[3 * i + 2], 0.0f);

    // Conservative bbox: contribution requires sigma <= ln(255) ~ 5.5413.
    // x-extent of {0.5 d^T C d <= T} is sqrt(2 T s00); add margin.
    const float T = 5.65f;
    float hx = sqrtf(2.0f * T * s00) + 1.0f;
    float hy = sqrtf(2.0f * T * s11) + 1.0f;

    if (px + hx < 0.0f || px - hx > (float)(WIMG - 1) ||
        py + hy < 0.0f || py - hy > (float)(HIMG - 1)) return;

    int x0 = max(0,       (int)floorf((px - hx) * (1.0f / TILE)));
    int x1 = min(TXN - 1, (int)floorf((px + hx) * (1.0f / TILE)));
    int y0 = max(0,       (int)floorf((py - hy) * (1.0f / TILE)));
    int y1 = min(TYN - 1, (int)floorf((py + hy) * (1.0f / TILE)));

    for (int ty = y0; ty <= y1; ty++) {
        for (int tx = x0; tx <= x1; tx++) {
            int t = ty * TXN + tx;
            int slot = atomicAdd(&g_tile_cnt[t], 1);
            if (slot < CAP) g_tile_list[t * CAP + slot] = i;
        }
    }
}

__global__ __launch_bounds__(256)
void raster_kernel(float* __restrict__ out) {
    __shared__ float4 sa[BATCH];
    __shared__ float4 sb[BATCH];
    __shared__ float4 sc[BATCH];

    int tile  = blockIdx.x;
    int tilex = tile % TXN;
    int tiley = tile / TXN;
    int tid   = threadIdx.x;
    int lx    = tid & (TILE - 1);
    int ly    = tid >> 4;

    int   pxi = tilex * TILE + lx;
    int   pyi = tiley * TILE + ly;
    float pxf = (float)pxi;
    float pyf = (float)pyi;

    int cnt = g_tile_cnt[tile];
    if (cnt > CAP) cnt = CAP;

    float ar = 0.f, ag = 0.f, ab = 0.f;
    float gr = 0.f, gg = 0.f, gb = 0.f;
    float aa = 0.f;

    for (int base = 0; base < cnt; base += BATCH) {
        int n = min(BATCH, cnt - base);
        __syncthreads();
        for (int j = tid; j < n; j += 256) {
            int id = g_tile_list[tile * CAP + base + j];
            sa[j] = g_pa[id];
            sb[j] = g_pb[id];
            sc[j] = g_pc[id];
        }
        __syncthreads();
        for (int j = 0; j < n; j++) {
            float4 a = sa[j];
            float dx = a.x - pxf;
            float dy = a.y - pyf;
            float c2h = sb[j].x;
            float sigma = a.z * dx * dx + a.w * dx * dy + c2h * dy * dy;
            float e = __expf(-sigma);
            // live iff sigma >= 0 and e >= 1/255 (min(0.999, e) only drops
            // alpha when e > 0.999 > 1/255, so test on e directly).
            bool live = (sigma >= 0.0f) && (e >= (1.0f / 255.0f));
            float alpha = live ? fminf(0.999f, e) : 0.0f;
            float4 b = sb[j];
            float4 c = sc[j];
            ar += alpha * b.y;
            ag += alpha * b.z;
            ab += alpha * b.w;
            gr += alpha * c.x;
            gg += alpha * c.y;
            gb += alpha * c.z;
            aa += alpha;
        }
    }

    int pix = pyi * WIMG + pxi;
    // render (clipped), channel-major [3, H, W]
    out[0 * HW + pix] = fminf(1.0f, fmaxf(0.0f, ar));
    out[1 * HW + pix] = fminf(1.0f, fmaxf(0.0f, ag));
    out[2 * HW + pix] = fminf(1.0f, fmaxf(0.0f, ab));
    // gauss_render (clipped)
    out[3 * HW + pix] = fminf(1.0f, fmaxf(0.0f, gr));
    out[4 * HW + pix] = fminf(1.0f, fmaxf(0.0f, gg));
    out[5 * HW + pix] = fminf(1.0f, fmaxf(0.0f, gb));
    // alpha map (unclipped)
    out[6 * HW + pix] = aa;

    // Restore the zeroed state for the next graph replay.
    __syncthreads();
    if (tid == 0) g_tile_cnt[tile] = 0;
}

extern "C" void kernel_launch(void* const* d_in, const int* in_sizes, int n_in,
                              void* d_out, int out_size) {
    const float* xyz  = (const float*)d_in[0];
    const float* chol = (const float*)d_in[1];
    const float* feat = (const float*)d_in[2];
    const float* rcol = (const float*)d_in[3];

    float* out  = (float*)d_out;
    float* opac = out + 7 * HW;  // render(3HW) + gauss(3HW) + alpha(HW), then opac(NG)

    project_bin_kernel<<<(NG + 255) / 256, 256>>>(xyz, chol, feat, rcol, opac);
    raster_kernel<<<NTILES, 256>>>(out);
}